// round 7
// baseline (speedup 1.0000x reference)
#include <cuda_runtime.h>
#include <cuda_bf16.h>
#include <cstdint>
#include <math.h>

// QuantumNet fused, round 7: single-warp autonomous CTAs.
// 1024 CTAs x 32 threads, each an independent depth-3 cp.async pipeline.
// Coalesced lane-over-K tile loads + warp-uniform broadcast weight LDS.

#define KDIM 512
#define ROWS 32
#define THREADS 32
#define KTILE 64
#define NTILES (KDIM / KTILE)   // 8
#define NSTAGES 3
#define XS_STRIDE 68            // 64 + 4 pad -> conflict-free LDS.128

__device__ __forceinline__ void cpasync16(float* dst_smem, const float* src) {
    unsigned int s = (unsigned int)__cvta_generic_to_shared(dst_smem);
    asm volatile("cp.async.cg.shared.global [%0], [%1], 16;\n" :: "r"(s), "l"(src));
}

__global__ __launch_bounds__(THREADS)
void qnet_kernel(const float* __restrict__ x,
                 const float* __restrict__ pre_w,
                 const float* __restrict__ pre_b,
                 const float* __restrict__ u3p,
                 const float* __restrict__ post_w,
                 const float* __restrict__ post_b,
                 float* __restrict__ out, int B)
{
    __shared__ float wts[KDIM * 4];                    // 8 KB
    __shared__ float xs[NSTAGES][ROWS * XS_STRIDE];    // 3 x 8.5 KB

    const int tid  = threadIdx.x;
    const int row0 = blockIdx.x * ROWS;
    const int row  = row0 + tid;

    // wts[k*4+q] = pre_w[q*512+k]; warp-wide, finishes before first use
    #pragma unroll
    for (int i = tid; i < KDIM * 4; i += THREADS) {
        int q = i >> 9;
        int k = i & (KDIM - 1);
        wts[k * 4 + q] = pre_w[i];
    }

    // tile: 32 rows x 16 float4; 16 cp.async per thread
    auto issue_tile = [&](int kt, int stage) {
        const int kbase = kt * KTILE;
        #pragma unroll
        for (int i = 0; i < 16; ++i) {
            int f = tid + i * THREADS;   // 0..511
            int r = f >> 4;              // row 0..31
            int c = f & 15;              // float4 col
            int gr = row0 + r;
            if (gr < B)
                cpasync16(&xs[stage][r * XS_STRIDE + c * 4],
                          &x[(size_t)gr * KDIM + kbase + c * 4]);
        }
        asm volatile("cp.async.commit_group;\n" ::);
    };

    issue_tile(0, 0);
    issue_tile(1, 1);
    issue_tile(2, 2);

    float acc0 = 0.f, acc1 = 0.f, acc2 = 0.f, acc3 = 0.f;

    #pragma unroll
    for (int kt = 0; kt < NTILES; ++kt) {
        if (kt < NTILES - 2)
            asm volatile("cp.async.wait_group 2;\n" ::);
        else if (kt == NTILES - 2)
            asm volatile("cp.async.wait_group 1;\n" ::);
        else
            asm volatile("cp.async.wait_group 0;\n" ::);
        __syncthreads();   // single warp: ~3 cyc, orders smem visibility

        const int stage = kt % NSTAGES;
        const int kbase = kt * KTILE;
        #pragma unroll
        for (int k = 0; k < KTILE; k += 4) {
            float4 xv = *(const float4*)&xs[stage][tid * XS_STRIDE + k];
            float4 w0 = *(const float4*)&wts[(kbase + k + 0) * 4];
            float4 w1 = *(const float4*)&wts[(kbase + k + 1) * 4];
            float4 w2 = *(const float4*)&wts[(kbase + k + 2) * 4];
            float4 w3 = *(const float4*)&wts[(kbase + k + 3) * 4];
            acc0 = fmaf(xv.x, w0.x, acc0); acc1 = fmaf(xv.x, w0.y, acc1);
            acc2 = fmaf(xv.x, w0.z, acc2); acc3 = fmaf(xv.x, w0.w, acc3);
            acc0 = fmaf(xv.y, w1.x, acc0); acc1 = fmaf(xv.y, w1.y, acc1);
            acc2 = fmaf(xv.y, w1.z, acc2); acc3 = fmaf(xv.y, w1.w, acc3);
            acc0 = fmaf(xv.z, w2.x, acc0); acc1 = fmaf(xv.z, w2.y, acc1);
            acc2 = fmaf(xv.z, w2.z, acc2); acc3 = fmaf(xv.z, w2.w, acc3);
            acc0 = fmaf(xv.w, w3.x, acc0); acc1 = fmaf(xv.w, w3.y, acc1);
            acc2 = fmaf(xv.w, w3.z, acc2); acc3 = fmaf(xv.w, w3.w, acc3);
        }
        __syncthreads();

        if (kt + NSTAGES < NTILES)
            issue_tile(kt + NSTAGES, stage);
    }

    if (row >= B) return;

    float pre[4];
    pre[0] = acc0 + pre_b[0];
    pre[1] = acc1 + pre_b[1];
    pre[2] = acc2 + pre_b[2];
    pre[3] = acc3 + pre_b[3];

    // Per-qubit state after H, RY(atan t), RZ(atan t^2)
    float aR[4], aI[4], bR[4], bI[4];
    const float HALF_PI = 1.5707963267948966f;
    const float INV_SQRT2 = 0.7071067811865476f;
    #pragma unroll
    for (int q = 0; q < 4; ++q) {
        float t  = tanhf(pre[q] * 0.1f) * HALF_PI;
        float cr = rsqrtf(fmaf(t, t, 1.f));
        float sr = t * cr;
        float c2 = sqrtf(0.5f * (1.f + cr));
        float s2 = 0.5f * sr * __fdividef(1.f, c2);
        float u  = t * t;
        float cz = rsqrtf(fmaf(u, u, 1.f));
        float szf = u * cz;
        float ch = sqrtf(0.5f * (1.f + cz));
        float sh = 0.5f * szf * __fdividef(1.f, ch);
        float Aa = (c2 - s2) * INV_SQRT2;
        float Bb = (c2 + s2) * INV_SQRT2;
        aR[q] = Aa * ch;  aI[q] = -Aa * sh;
        bR[q] = Bb * ch;  bI[q] =  Bb * sh;
    }

    float tR[4], tI[4], uR[4], uI[4];
    #pragma unroll
    for (int h = 0; h < 4; ++h) {
        int j0 = h >> 1, j1 = h & 1;
        float r0 = j0 ? bR[0] : aR[0], i0 = j0 ? bI[0] : aI[0];
        float r1 = j1 ? bR[1] : aR[1], i1 = j1 ? bI[1] : aI[1];
        tR[h] = r0 * r1 - i0 * i1;
        tI[h] = r0 * i1 + i0 * r1;
        float r2 = j0 ? bR[2] : aR[2], i2 = j0 ? bI[2] : aI[2];
        float r3 = j1 ? bR[3] : aR[3], i3 = j1 ? bI[3] : aI[3];
        uR[h] = r2 * r3 - i2 * i3;
        uI[h] = r2 * i3 + i2 * r3;
    }

    float AR[16], AI[16], NR[16];
    #pragma unroll
    for (int i = 0; i < 16; ++i) {
        int a_ = (i >> 3) & 1, b_ = (i >> 2) & 1, c_ = (i >> 1) & 1, d_ = i & 1;
        int s  = ((a_ ^ b_ ^ c_) << 3) | ((a_ ^ c_ ^ d_) << 2)
               | ((a_ ^ b_ ^ d_) << 1) | (a_ ^ b_);
        int hi = s >> 2, lo = s & 3;
        AR[i] = tR[hi] * uR[lo] - tI[hi] * uI[lo];
        AI[i] = tR[hi] * uI[lo] + tI[hi] * uR[lo];
        NR[i] = AR[i] * AR[i] + AI[i] * AI[i];
    }

    float ct4[4], mr4[4], mi4[4];
    #pragma unroll
    for (int q = 0; q < 4; ++q) {
        float th = u3p[q * 3 + 0];
        float la = u3p[q * 3 + 2];
        float st_, ct_, sl_, cl_;
        __sincosf(th, &st_, &ct_);
        __sincosf(la, &sl_, &cl_);
        ct4[q] = ct_;
        mr4[q] = -st_ * cl_;
        mi4[q] = -st_ * sl_;
    }

    float E[4];
    #pragma unroll
    for (int q = 0; q < 4; ++q) {
        const int p = 3 - q;
        float Sn = 0.f, Szr = 0.f, Szi = 0.f;
        #pragma unroll
        for (int m = 0; m < 8; ++m) {
            int lowmask = (1 << p) - 1;
            int i0 = ((m & ~lowmask) << 1) | (m & lowmask);
            int i1 = i0 | (1 << p);
            Sn  += NR[i0] - NR[i1];
            Szr += AR[i0] * AR[i1] + AI[i0] * AI[i1];
            Szi += AR[i0] * AI[i1] - AI[i0] * AR[i1];
        }
        E[q] = ct4[q] * Sn + 2.f * (mr4[q] * Szr - mi4[q] * Szi);
    }

    float o0 = post_b[0], o1 = post_b[1];
    #pragma unroll
    for (int q = 0; q < 4; ++q) {
        o0 = fmaf(post_w[q],     E[q], o0);
        o1 = fmaf(post_w[4 + q], E[q], o1);
    }
    float2 res; res.x = o0; res.y = o1;
    ((float2*)out)[row] = res;
}

extern "C" void kernel_launch(void* const* d_in, const int* in_sizes, int n_in,
                              void* d_out, int out_size) {
    const float* x      = (const float*)d_in[0];
    const float* pre_w  = (const float*)d_in[1];
    const float* pre_b  = (const float*)d_in[2];
    const float* u3p    = (const float*)d_in[3];
    const float* post_w = (const float*)d_in[4];
    const float* post_b = (const float*)d_in[5];
    float* out = (float*)d_out;

    int B = in_sizes[0] / KDIM;
    int grid = (B + ROWS - 1) / ROWS;
    qnet_kernel<<<grid, THREADS>>>(x, pre_w, pre_b, u3p, post_w, post_b, out, B);
}

// round 9
// speedup vs baseline: 1.2220x; 1.2220x over previous
#include <cuda_runtime.h>
#include <cuda_bf16.h>
#include <cstdint>
#include <math.h>

// QuantumNet fused, round 9 (resubmit of round 8 — infra failure, untested):
//  - mainloop: R3-style coalesced cp.async tiles, KTILE=32, depth-4 pipeline
//  - epilogue: fully collapsed via Clifford conjugation -> per-qubit scalar
//    products (no 16-amplitude state, ~25 live regs)

#define KDIM 512
#define ROWS 64
#define THREADS 64
#define KTILE 32
#define NTILES (KDIM / KTILE)   // 16
#define NSTAGES 4
#define XS_STRIDE 36            // 32 + 4 pad -> conflict-free LDS.128/STS.128

__device__ __forceinline__ void cpasync16(float* dst_smem, const float* src) {
    unsigned int s = (unsigned int)__cvta_generic_to_shared(dst_smem);
    asm volatile("cp.async.cg.shared.global [%0], [%1], 16;\n" :: "r"(s), "l"(src));
}

__global__ __launch_bounds__(THREADS)
void qnet_kernel(const float* __restrict__ x,
                 const float* __restrict__ pre_w,
                 const float* __restrict__ pre_b,
                 const float* __restrict__ u3p,
                 const float* __restrict__ post_w,
                 const float* __restrict__ post_b,
                 float* __restrict__ out, int B)
{
    __shared__ float wts[KDIM * 4];                    // 8 KB [k][q]
    __shared__ float xs[NSTAGES][ROWS * XS_STRIDE];    // 4 x 9.2 KB

    const int tid  = threadIdx.x;
    const int row0 = blockIdx.x * ROWS;
    const int row  = row0 + tid;

    #pragma unroll
    for (int i = tid; i < KDIM * 4; i += THREADS) {
        int q = i >> 9;
        int k = i & (KDIM - 1);
        wts[k * 4 + q] = pre_w[i];
    }

    // tile: 64 rows x 8 float4 (32 K) = 512 float4, 8 per thread
    auto issue_tile = [&](int kt, int stage) {
        const int kbase = kt * KTILE;
        #pragma unroll
        for (int i = 0; i < 8; ++i) {
            int f = tid + i * THREADS;   // 0..511
            int r = f >> 3;              // row 0..63
            int c = f & 7;               // float4 col 0..7
            int gr = row0 + r;
            if (gr < B)
                cpasync16(&xs[stage][r * XS_STRIDE + c * 4],
                          &x[(size_t)gr * KDIM + kbase + c * 4]);
        }
        asm volatile("cp.async.commit_group;\n" ::);
    };

    issue_tile(0, 0);
    issue_tile(1, 1);
    issue_tile(2, 2);
    issue_tile(3, 3);

    float acc0 = 0.f, acc1 = 0.f, acc2 = 0.f, acc3 = 0.f;

    #pragma unroll
    for (int kt = 0; kt < NTILES; ++kt) {
        // allowed outstanding groups after wait = min(NSTAGES-1, NTILES-1-kt)
        if (kt < NTILES - 3)
            asm volatile("cp.async.wait_group 3;\n" ::);
        else if (kt == NTILES - 3)
            asm volatile("cp.async.wait_group 2;\n" ::);
        else if (kt == NTILES - 2)
            asm volatile("cp.async.wait_group 1;\n" ::);
        else
            asm volatile("cp.async.wait_group 0;\n" ::);
        __syncthreads();

        const int stage = kt % NSTAGES;
        const int kbase = kt * KTILE;
        #pragma unroll
        for (int k = 0; k < KTILE; k += 4) {
            float4 xv = *(const float4*)&xs[stage][tid * XS_STRIDE + k];
            float4 w0 = *(const float4*)&wts[(kbase + k + 0) * 4];
            float4 w1 = *(const float4*)&wts[(kbase + k + 1) * 4];
            float4 w2 = *(const float4*)&wts[(kbase + k + 2) * 4];
            float4 w3 = *(const float4*)&wts[(kbase + k + 3) * 4];
            acc0 = fmaf(xv.x, w0.x, acc0); acc1 = fmaf(xv.x, w0.y, acc1);
            acc2 = fmaf(xv.x, w0.z, acc2); acc3 = fmaf(xv.x, w0.w, acc3);
            acc0 = fmaf(xv.y, w1.x, acc0); acc1 = fmaf(xv.y, w1.y, acc1);
            acc2 = fmaf(xv.y, w1.z, acc2); acc3 = fmaf(xv.y, w1.w, acc3);
            acc0 = fmaf(xv.z, w2.x, acc0); acc1 = fmaf(xv.z, w2.y, acc1);
            acc2 = fmaf(xv.z, w2.z, acc2); acc3 = fmaf(xv.z, w2.w, acc3);
            acc0 = fmaf(xv.w, w3.x, acc0); acc1 = fmaf(xv.w, w3.y, acc1);
            acc2 = fmaf(xv.w, w3.z, acc2); acc3 = fmaf(xv.w, w3.w, acc3);
        }
        __syncthreads();

        if (kt + NSTAGES < NTILES)
            issue_tile(kt + NSTAGES, stage);
    }

    if (row >= B) return;

    // ---- collapsed epilogue ----
    // per qubit: t = tanh(pre/10)*pi/2, u = t^2
    //   z = -t/sqrt(1+t^2); x = rsqrt(1+t^2)*rsqrt(1+u^2); y = x*u
    const float HALF_PI = 1.5707963267948966f;
    float z[4], xq[4], yq[4];
    float pre[4] = { acc0 + pre_b[0], acc1 + pre_b[1],
                     acc2 + pre_b[2], acc3 + pre_b[3] };
    #pragma unroll
    for (int q = 0; q < 4; ++q) {
        float t  = tanhf(pre[q] * 0.1f) * HALF_PI;
        float u  = t * t;
        float cr = rsqrtf(fmaf(t, t, 1.f));
        float cz = rsqrtf(fmaf(u, u, 1.f));
        z[q]  = -t * cr;
        xq[q] = cr * cz;
        yq[q] = xq[q] * u;
    }

    // M_q = c Z - s cos(la) X + s sin(la) Y
    float cg[4], mx[4], my[4];
    #pragma unroll
    for (int q = 0; q < 4; ++q) {
        float th = u3p[q * 3 + 0];
        float la = u3p[q * 3 + 2];
        float st_, ct_, sl_, cl_;
        __sincosf(th, &st_, &ct_);
        __sincosf(la, &sl_, &cl_);
        cg[q] = ct_;
        mx[q] = -st_ * cl_;
        my[q] =  st_ * sl_;
    }

    // Clifford-conjugated Pauli strings (derived by hand):
    // Z~: Z0Z1Z2 | Z0Z1Z2Z3 | Z0Z3 | Z2Z3
    // X~: X0X1X2X3 | X0X2X3 | X0X1 | X1X2
    // Y~: -Y0Y1Y2X3 | -Y0Z1Y2Y3 | Y0X1Z3 | X1Y2Z3
    float z01 = z[0] * z[1];
    float E0 = cg[0] * (z01 * z[2])
             + mx[0] * (xq[0] * xq[1] * xq[2] * xq[3])
             - my[0] * (yq[0] * yq[1] * yq[2] * xq[3]);
    float E1 = cg[1] * (z01 * z[2] * z[3])
             + mx[1] * (xq[0] * xq[2] * xq[3])
             - my[1] * (yq[0] * z[1] * yq[2] * yq[3]);
    float E2 = cg[2] * (z[0] * z[3])
             + mx[2] * (xq[0] * xq[1])
             + my[2] * (yq[0] * xq[1] * z[3]);
    float E3 = cg[3] * (z[2] * z[3])
             + mx[3] * (xq[1] * xq[2])
             + my[3] * (xq[1] * yq[2] * z[3]);

    float o0 = post_b[0], o1 = post_b[1];
    o0 = fmaf(post_w[0], E0, o0); o1 = fmaf(post_w[4], E0, o1);
    o0 = fmaf(post_w[1], E1, o0); o1 = fmaf(post_w[5], E1, o1);
    o0 = fmaf(post_w[2], E2, o0); o1 = fmaf(post_w[6], E2, o1);
    o0 = fmaf(post_w[3], E3, o0); o1 = fmaf(post_w[7], E3, o1);

    float2 res; res.x = o0; res.y = o1;
    ((float2*)out)[row] = res;
}

extern "C" void kernel_launch(void* const* d_in, const int* in_sizes, int n_in,
                              void* d_out, int out_size) {
    const float* x      = (const float*)d_in[0];
    const float* pre_w  = (const float*)d_in[1];
    const float* pre_b  = (const float*)d_in[2];
    const float* u3p    = (const float*)d_in[3];
    const float* post_w = (const float*)d_in[4];
    const float* post_b = (const float*)d_in[5];
    float* out = (float*)d_out;

    int B = in_sizes[0] / KDIM;
    int grid = (B + ROWS - 1) / ROWS;
    qnet_kernel<<<grid, THREADS>>>(x, pre_w, pre_b, u3p, post_w, post_b, out, B);
}

// round 11
// speedup vs baseline: 1.2405x; 1.0152x over previous
#include <cuda_runtime.h>
#include <cuda_bf16.h>
#include <cstdint>
#include <math.h>

// QuantumNet fused, round 10: K-split warp pairs.
// CTA = 128 threads / 64 rows. Half 0 (threads 0-63) computes k in [0,32)
// of each 64-K tile, half 1 computes k in [32,64). Weight LDS stays
// warp-uniform (broadcast); tile loads stay lane-over-K coalesced cp.async.
// 2x warps/SM vs R3 at identical memory structure.

#define KDIM 512
#define ROWS 64
#define THREADS 128
#define KTILE 64
#define NTILES (KDIM / KTILE)   // 8
#define NSTAGES 3
#define XS_STRIDE 68            // 64 + 4 pad

__device__ __forceinline__ void cpasync16(float* dst_smem, const float* src) {
    unsigned int s = (unsigned int)__cvta_generic_to_shared(dst_smem);
    asm volatile("cp.async.cg.shared.global [%0], [%1], 16;\n" :: "r"(s), "l"(src));
}

__global__ __launch_bounds__(THREADS)
void qnet_kernel(const float* __restrict__ x,
                 const float* __restrict__ pre_w,
                 const float* __restrict__ pre_b,
                 const float* __restrict__ u3p,
                 const float* __restrict__ post_w,
                 const float* __restrict__ post_b,
                 float* __restrict__ out, int B)
{
    __shared__ float wts[KDIM * 4];                    // 8 KB [k][q]
    __shared__ float xs[NSTAGES][ROWS * XS_STRIDE];    // 3 x 17 KB
    __shared__ float red[ROWS * 4];                    // 1 KB cross-half partials

    const int tid  = threadIdx.x;
    const int half = tid >> 6;          // 0: k-low, 1: k-high
    const int rl   = tid & 63;          // row lane 0..63
    const int row0 = blockIdx.x * ROWS;
    const int row  = row0 + rl;

    #pragma unroll
    for (int i = tid; i < KDIM * 4; i += THREADS) {
        int q = i >> 9;
        int k = i & (KDIM - 1);
        wts[k * 4 + q] = pre_w[i];
    }

    // tile: 64 rows x 16 float4 = 1024 float4; 8 cp.async per thread
    auto issue_tile = [&](int kt, int stage) {
        const int kbase = kt * KTILE;
        #pragma unroll
        for (int i = 0; i < 8; ++i) {
            int f = tid + i * THREADS;   // 0..1023
            int r = f >> 4;              // row 0..63
            int c = f & 15;              // float4 col 0..15
            int gr = row0 + r;
            if (gr < B)
                cpasync16(&xs[stage][r * XS_STRIDE + c * 4],
                          &x[(size_t)gr * KDIM + kbase + c * 4]);
        }
        asm volatile("cp.async.commit_group;\n" ::);
    };

    issue_tile(0, 0);
    issue_tile(1, 1);
    issue_tile(2, 2);

    float acc0 = 0.f, acc1 = 0.f, acc2 = 0.f, acc3 = 0.f;
    const int koff = half * 32;          // this half's k window within a tile

    #pragma unroll
    for (int kt = 0; kt < NTILES; ++kt) {
        if (kt < NTILES - 2)
            asm volatile("cp.async.wait_group 2;\n" ::);
        else if (kt == NTILES - 2)
            asm volatile("cp.async.wait_group 1;\n" ::);
        else
            asm volatile("cp.async.wait_group 0;\n" ::);
        __syncthreads();

        const int stage = kt % NSTAGES;
        const int kbase = kt * KTILE + koff;
        #pragma unroll
        for (int k = 0; k < 32; k += 4) {
            float4 xv = *(const float4*)&xs[stage][rl * XS_STRIDE + koff + k];
            float4 w0 = *(const float4*)&wts[(kbase + k + 0) * 4];
            float4 w1 = *(const float4*)&wts[(kbase + k + 1) * 4];
            float4 w2 = *(const float4*)&wts[(kbase + k + 2) * 4];
            float4 w3 = *(const float4*)&wts[(kbase + k + 3) * 4];
            acc0 = fmaf(xv.x, w0.x, acc0); acc1 = fmaf(xv.x, w0.y, acc1);
            acc2 = fmaf(xv.x, w0.z, acc2); acc3 = fmaf(xv.x, w0.w, acc3);
            acc0 = fmaf(xv.y, w1.x, acc0); acc1 = fmaf(xv.y, w1.y, acc1);
            acc2 = fmaf(xv.y, w1.z, acc2); acc3 = fmaf(xv.y, w1.w, acc3);
            acc0 = fmaf(xv.z, w2.x, acc0); acc1 = fmaf(xv.z, w2.y, acc1);
            acc2 = fmaf(xv.z, w2.z, acc2); acc3 = fmaf(xv.z, w2.w, acc3);
            acc0 = fmaf(xv.w, w3.x, acc0); acc1 = fmaf(xv.w, w3.y, acc1);
            acc2 = fmaf(xv.w, w3.z, acc2); acc3 = fmaf(xv.w, w3.w, acc3);
        }
        __syncthreads();

        if (kt + NSTAGES < NTILES)
            issue_tile(kt + NSTAGES, stage);
    }

    // cross-half reduction: half 1 stores partials, half 0 finishes
    if (half == 1) {
        float4 v; v.x = acc0; v.y = acc1; v.z = acc2; v.w = acc3;
        *(float4*)&red[rl * 4] = v;
    }
    __syncthreads();
    if (half == 1) return;
    {
        float4 v = *(const float4*)&red[rl * 4];
        acc0 += v.x; acc1 += v.y; acc2 += v.z; acc3 += v.w;
    }

    if (row >= B) return;

    // ---- collapsed epilogue (Clifford-conjugated Pauli strings) ----
    const float HALF_PI = 1.5707963267948966f;
    float z[4], xq[4], yq[4];
    float pre[4] = { acc0 + pre_b[0], acc1 + pre_b[1],
                     acc2 + pre_b[2], acc3 + pre_b[3] };
    #pragma unroll
    for (int q = 0; q < 4; ++q) {
        float t  = tanhf(pre[q] * 0.1f) * HALF_PI;
        float u  = t * t;
        float cr = rsqrtf(fmaf(t, t, 1.f));
        float cz = rsqrtf(fmaf(u, u, 1.f));
        z[q]  = -t * cr;
        xq[q] = cr * cz;
        yq[q] = xq[q] * u;
    }

    float cg[4], mx[4], my[4];
    #pragma unroll
    for (int q = 0; q < 4; ++q) {
        float th = u3p[q * 3 + 0];
        float la = u3p[q * 3 + 2];
        float st_, ct_, sl_, cl_;
        __sincosf(th, &st_, &ct_);
        __sincosf(la, &sl_, &cl_);
        cg[q] = ct_;
        mx[q] = -st_ * cl_;
        my[q] =  st_ * sl_;
    }

    // Z~: Z0Z1Z2 | Z0Z1Z2Z3 | Z0Z3 | Z2Z3
    // X~: X0X1X2X3 | X0X2X3 | X0X1 | X1X2
    // Y~: -Y0Y1Y2X3 | -Y0Z1Y2Y3 | Y0X1Z3 | X1Y2Z3
    float z01 = z[0] * z[1];
    float E0 = cg[0] * (z01 * z[2])
             + mx[0] * (xq[0] * xq[1] * xq[2] * xq[3])
             - my[0] * (yq[0] * yq[1] * yq[2] * xq[3]);
    float E1 = cg[1] * (z01 * z[2] * z[3])
             + mx[1] * (xq[0] * xq[2] * xq[3])
             - my[1] * (yq[0] * z[1] * yq[2] * yq[3]);
    float E2 = cg[2] * (z[0] * z[3])
             + mx[2] * (xq[0] * xq[1])
             + my[2] * (yq[0] * xq[1] * z[3]);
    float E3 = cg[3] * (z[2] * z[3])
             + mx[3] * (xq[1] * xq[2])
             + my[3] * (xq[1] * yq[2] * z[3]);

    float o0 = post_b[0], o1 = post_b[1];
    o0 = fmaf(post_w[0], E0, o0); o1 = fmaf(post_w[4], E0, o1);
    o0 = fmaf(post_w[1], E1, o0); o1 = fmaf(post_w[5], E1, o1);
    o0 = fmaf(post_w[2], E2, o0); o1 = fmaf(post_w[6], E2, o1);
    o0 = fmaf(post_w[3], E3, o0); o1 = fmaf(post_w[7], E3, o1);

    float2 res; res.x = o0; res.y = o1;
    ((float2*)out)[row] = res;
}

extern "C" void kernel_launch(void* const* d_in, const int* in_sizes, int n_in,
                              void* d_out, int out_size) {
    const float* x      = (const float*)d_in[0];
    const float* pre_w  = (const float*)d_in[1];
    const float* pre_b  = (const float*)d_in[2];
    const float* u3p    = (const float*)d_in[3];
    const float* post_w = (const float*)d_in[4];
    const float* post_b = (const float*)d_in[5];
    float* out = (float*)d_out;

    int B = in_sizes[0] / KDIM;
    int grid = (B + ROWS - 1) / ROWS;
    qnet_kernel<<<grid, THREADS>>>(x, pre_w, pre_b, u3p, post_w, post_b, out, B);
}